// round 5
// baseline (speedup 1.0000x reference)
#include <cuda_runtime.h>
#include <math.h>

#define LS    32
#define SEQL  1024
#define BSZ   8
#define EMBED 1024
#define KDIM  64
#define NDIM  16
#define VPOW  64
#define RTOT  16384
#define R2    16

// ---------------- scratch (__device__ globals; no allocation anywhere) -------
__device__ float         g_Apow[4 * VPOW * 1024];   // [a][v][kd*16+n]
__device__ float         g_Bsig[2 * 1024];          // [col][kd*16+n]
__device__ unsigned char g_idx8[2 * RTOT * 4];      // [d][r][a]  (uchar4 per r)
__device__ float         g_coef[2 * RTOT];          // signed: +coef->col0, -coef->col1
__device__ float         g_w[2 * 1024 * 1024];      // [d][p][kd*16+n]
__device__ float         g_kk[1024 * 4096];         // [p][kd*64+h]
__device__ float         g_ksum[1024 * 1024];       // [p*32+q][e]

// ---------------- f32x2 helpers (FFMA2: 2x fp32 MAC per issue) ---------------
__device__ __forceinline__ unsigned long long pk2(float lo, float hi) {
    unsigned long long r;
    asm("mov.b64 %0, {%1, %2};" : "=l"(r) : "f"(lo), "f"(hi));
    return r;
}
__device__ __forceinline__ void fma2(unsigned long long& d,
                                     unsigned long long a, unsigned long long b) {
    asm("fma.rn.f32x2 %0, %1, %2, %0;" : "+l"(d) : "l"(a), "l"(b));
}
__device__ __forceinline__ float2 upk2(unsigned long long v) {
    float2 f;
    asm("mov.b64 {%0, %1}, %2;" : "=f"(f.x), "=f"(f.y) : "l"(v));
    return f;
}

// ---------------- 1. sigmoid + power tables ---------------------------------
__global__ void k_setup(const float* __restrict__ A,
                        const float* __restrict__ B1,
                        const float* __restrict__ B2) {
    int id = blockIdx.x * 256 + threadIdx.x;
    if (id < 4096) {
        float s = 1.f / (1.f + expf(-A[id]));
        int a = id >> 10, t = id & 1023;
        float cur = 1.f;
        #pragma unroll
        for (int v = 0; v < VPOW; v++) {
            g_Apow[(a * VPOW + v) * 1024 + t] = cur;
            cur *= s;
        }
    } else if (id < 4096 + 2048) {
        int j = id - 4096;
        const float* B = (j < 1024) ? B1 : B2;
        g_Bsig[j] = 1.f / (1.f + expf(-B[j & 1023]));
    }
}

// ---------------- 2. one-hot index extraction from one_matrix ---------------
__global__ void k_extract(const float* __restrict__ OM) {
    int gwarp = (blockIdx.x * 256 + threadIdx.x) >> 5;
    int lane  = threadIdx.x & 31;
    int d   = gwarp / (5 * RTOT);
    int rem = gwarp - d * 5 * RTOT;
    int a   = rem / RTOT;
    int r   = rem - a * RTOT;
    int base = ((d * 5 + a) * RTOT + r) * VPOW;
    float v0 = OM[base + lane];
    float v1 = OM[base + 32 + lane];
    unsigned m0 = __ballot_sync(0xffffffffu, v0 != 0.f);
    unsigned m1 = __ballot_sync(0xffffffffu, v1 != 0.f);
    int idx = m0 ? (__ffs(m0) - 1) : (32 + __ffs(m1) - 1);
    if (a < 4) {
        if (lane == 0) g_idx8[(d * RTOT + r) * 4 + a] = (unsigned char)idx;
    } else {
        float val = __shfl_sync(0xffffffffu, (idx < 32) ? v0 : v1, idx & 31);
        if (lane == 0) g_coef[d * RTOT + r] = (idx == 0) ? val : -val;
    }
}

// ---------------- 3. w[d][p][kd*16+n], smem-tiled Apow gathers ---------------
// grid (32 tc, 4 pc, 2 d), 256 threads: (plane = tid>>5) x (t = tid&31)
__global__ void k_w() {
    __shared__ float sA[4 * VPOW * 32];            // 32 KB Apow slice for t-chunk
    int tc = blockIdx.x, pc = blockIdx.y, d = blockIdx.z;
    int t = threadIdx.x & 31, plane = threadIdx.x >> 5;
    for (int row = plane; row < 256; row += 8)
        sA[row * 32 + t] = g_Apow[row * 1024 + tc * 32 + t];
    __syncthreads();
    int tg = tc * 32 + t;
    float b0 = g_Bsig[tg], b1 = g_Bsig[1024 + tg];
    const unsigned* idx4p = (const unsigned*)g_idx8;
    for (int piter = 0; piter < 32; piter++) {
        int p = pc * 256 + piter * 8 + plane;
        float acc = 0.f;
        int rb = d * RTOT + p * 16;
        #pragma unroll
        for (int r2 = 0; r2 < R2; r2++) {
            unsigned q = idx4p[rb + r2];
            float cf  = g_coef[rb + r2];
            int i0 = q & 63, i1 = (q >> 8) & 63, i2 = (q >> 16) & 63, i3 = (q >> 24) & 63;
            float term = sA[(0 * VPOW + i0) * 32 + t] * sA[(1 * VPOW + i1) * 32 + t]
                       * sA[(2 * VPOW + i2) * 32 + t] * sA[(3 * VPOW + i3) * 32 + t];
            acc = fmaf(term * fabsf(cf), (cf > 0.f) ? b0 : b1, acc);
        }
        g_w[(d * 1024 + p) * 1024 + tg] = acc;
    }
}

// ---------------- 4. kk = W x C, smem-tiled register GEMM --------------------
// grid (64 kd, 8 pc), 256 threads. Per block: 128 p x 64 h, K = 32 (d,n).
__global__ void k_kk(const float* __restrict__ C1, const float* __restrict__ C2) {
    __shared__ float WshT[32][132];                // [c][p_l], padded
    __shared__ float Csh[32][64];                  // [c][h]
    int kd = blockIdx.x, pc = blockIdx.y, tid = threadIdx.x;
    int p0 = pc * 128;
    for (int idx = tid; idx < 2048; idx += 256) {
        int c = idx >> 6, h = idx & 63;
        int d = c >> 4, n = c & 15;
        const float* C = d ? C2 : C1;
        Csh[c][h] = C[(h * 64 + kd) * 16 + n] * 0.25f;
    }
    for (int idx = tid; idx < 4096; idx += 256) {
        int p_l = idx >> 5, c = idx & 31;
        int d = c >> 4, n = c & 15;
        WshT[c][p_l] = g_w[(d * 1024 + p0 + p_l) * 1024 + kd * 16 + n];
    }
    __syncthreads();
    int pg = tid >> 3, hg = tid & 7;               // 32 p-groups x 8 h-groups
    float acc[4][8];
    #pragma unroll
    for (int pi = 0; pi < 4; pi++)
        #pragma unroll
        for (int hi = 0; hi < 8; hi++) acc[pi][hi] = 0.f;
    #pragma unroll
    for (int c = 0; c < 32; c++) {
        float4 wv  = *(const float4*)&WshT[c][pg * 4];
        float4 cv0 = *(const float4*)&Csh[c][hg * 8];
        float4 cv1 = *(const float4*)&Csh[c][hg * 8 + 4];
        float w[4]  = {wv.x, wv.y, wv.z, wv.w};
        float cc[8] = {cv0.x, cv0.y, cv0.z, cv0.w, cv1.x, cv1.y, cv1.z, cv1.w};
        #pragma unroll
        for (int pi = 0; pi < 4; pi++)
            #pragma unroll
            for (int hi = 0; hi < 8; hi++)
                acc[pi][hi] = fmaf(w[pi], cc[hi], acc[pi][hi]);
    }
    #pragma unroll
    for (int pi = 0; pi < 4; pi++) {
        int p = p0 + pg * 4 + pi;
        float4* dst = (float4*)&g_kk[p * 4096 + kd * 64 + hg * 8];
        dst[0] = make_float4(acc[pi][0], acc[pi][1], acc[pi][2], acc[pi][3]);
        dst[1] = make_float4(acc[pi][4], acc[pi][5], acc[pi][6], acc[pi][7]);
    }
}

// ---------------- 5. direction flips + boundary scaling → ksum[p][e] --------
__device__ __forceinline__ float bfactor(int a, int b) {
    float f = 1.f;
    if (a == 0) f *= 2.f;
    if (b == 0) f *= 2.f;
    if (a == 0 && b == 0) f *= 0.25f;
    return f;
}

__global__ void k_ksum() {
    __shared__ float sh[4][1024];
    int pi = blockIdx.x, pj = blockIdx.y, tid = threadIdx.x;
    int rows[4] = { pi * 32 + pj, (31 - pi) * 32 + pj,
                    pi * 32 + (31 - pj), (31 - pi) * 32 + (31 - pj) };
    #pragma unroll
    for (int dir = 0; dir < 4; dir++)
        for (int idx = tid; idx < 1024; idx += 256)
            sh[dir][idx] = g_kk[rows[dir] * 4096 + dir * 1024 + idx];
    __syncthreads();
    float f0 = bfactor(pi, pj), f1 = bfactor(31 - pi, pj);
    float f2 = bfactor(pi, 31 - pj), f3 = bfactor(31 - pi, 31 - pj);
    for (int e = tid; e < 1024; e += 256) {
        int h = e >> 4, s = e & 15;
        int o = s * 64 + h;
        float v = f0 * sh[0][o] + f1 * sh[1][o] + f2 * sh[2][o] + f3 * sh[3][o];
        g_ksum[(pi * 32 + pj) * 1024 + e] = v;
    }
}

// ---------------- 6. triangular direct conv, f32x2 over batch pairs ----------
// grid (4 e-chunks, 16 row-pairs, 4 batch-pairs), 256 threads.
// Each block: rows (ip, 31-ip) -> uniform 34 u-iterations. Batch pair packed
// into f32x2 lanes so each FFMA2 does 2 MACs.
__global__ void __launch_bounds__(256, 1)
k_conv(const float* __restrict__ x, const float* __restrict__ omega,
       float* __restrict__ out) {
    int e  = blockIdx.x * 256 + threadIdx.x;
    int ip = blockIdx.y;
    int b0 = blockIdx.z * 2;
    float om = omega[e];
    unsigned long long omp = pk2(om, om);

    #pragma unroll 1
    for (int rr = 0; rr < 2; rr++) {
        int i = rr ? (31 - ip) : ip;
        unsigned long long acc[32];
        #pragma unroll
        for (int j = 0; j < 32; j++) acc[j] = 0ull;
        unsigned long long xr[32];

        #pragma unroll 1
        for (int u = 0; u <= i; u++) {
            int p = i - u;
            const float* xa = x + ((u * 32) * 8 + b0) * 1024 + e;
            #pragma unroll
            for (int j = 0; j < 32; j++)
                xr[j] = pk2(xa[j * 8192], xa[j * 8192 + 1024]);
            unsigned long long kr[32];
            const float* ka = g_ksum + (p * 32) * 1024 + e;
            #pragma unroll
            for (int q = 0; q < 32; q++) {
                float kv = ka[q * 1024];
                kr[q] = pk2(kv, kv);
            }
            #pragma unroll
            for (int j = 0; j < 32; j++) {
                #pragma unroll
                for (int q = 0; q <= j; q++)
                    fma2(acc[j], kr[q], xr[j - q]);
            }
        }
        // xr holds input row i (u == i last) -> fused residual
        float* oa = out + ((i * 32) * 8 + b0) * 1024 + e;
        #pragma unroll
        for (int j = 0; j < 32; j++) {
            fma2(acc[j], omp, xr[j]);
            float2 v = upk2(acc[j]);
            oa[j * 8192]        = v.x;
            oa[j * 8192 + 1024] = v.y;
        }
    }
}

// ---------------- launch -----------------------------------------------------
extern "C" void kernel_launch(void* const* d_in, const int* in_sizes, int n_in,
                              void* d_out, int out_size) {
    const float* x   = (const float*)d_in[0];
    const float* A   = (const float*)d_in[1];
    const float* B1  = (const float*)d_in[2];
    const float* B2  = (const float*)d_in[3];
    const float* C1  = (const float*)d_in[4];
    const float* C2  = (const float*)d_in[5];
    const float* om  = (const float*)d_in[6];
    const float* OM  = (const float*)d_in[7];
    float* out = (float*)d_out;

    k_setup<<<24, 256>>>(A, B1, B2);
    k_extract<<<(2 * 5 * RTOT) / 8, 256>>>(OM);
    k_w<<<dim3(32, 4, 2), 256>>>();
    k_kk<<<dim3(64, 8), 256>>>(C1, C2);
    k_ksum<<<dim3(32, 32), 256>>>();
    k_conv<<<dim3(4, 16, 4), 256>>>(x, om, out);
}

// round 8
// speedup vs baseline: 1.5121x; 1.5121x over previous
#include <cuda_runtime.h>
#include <math.h>

#define LS    32
#define SEQL  1024
#define BSZ   8
#define EMBED 1024
#define KDIM  64
#define NDIM  16
#define VPOW  64
#define RTOT  16384
#define R2    16

// ---------------- scratch (__device__ globals; no allocation anywhere) -------
__device__ float         g_Apow[4 * VPOW * 1024];   // [a][v][kd*16+n]
__device__ float         g_Bsig[2 * 1024];          // [col][kd*16+n]
__device__ unsigned char g_idx8[2 * RTOT * 4];      // [d][r][a]  (uchar4 per r)
__device__ float         g_coef[2 * RTOT];          // signed: +coef->col0, -coef->col1
__device__ float         g_w[2 * 1024 * 1024];      // [d][p][kd*16+n]
__device__ float         g_Ct[KDIM * 2 * NDIM * 64];// [kd][d][n][h], pre-scaled by 0.25
__device__ float         g_kk[1024 * 4096];         // [p][kd*64+h]
__device__ float         g_ksum[1024 * 1024];       // [p*32+q][e]

// ---------------- f32x2 helpers (FFMA2: 2x fp32 MAC per issue) ---------------
__device__ __forceinline__ unsigned long long pk2(float lo, float hi) {
    unsigned long long r;
    asm("mov.b64 %0, {%1, %2};" : "=l"(r) : "f"(lo), "f"(hi));
    return r;
}
__device__ __forceinline__ void fma2(unsigned long long& d,
                                     unsigned long long a, unsigned long long b) {
    asm("fma.rn.f32x2 %0, %1, %2, %0;" : "+l"(d) : "l"(a), "l"(b));
}
__device__ __forceinline__ float2 upk2(unsigned long long v) {
    float2 f;
    asm("mov.b64 {%0, %1}, %2;" : "=f"(f.x), "=f"(f.y) : "l"(v));
    return f;
}

// ---------------- 1. sigmoid + power tables ---------------------------------
__global__ void k_setup(const float* __restrict__ A,
                        const float* __restrict__ B1,
                        const float* __restrict__ B2) {
    int id = blockIdx.x * 256 + threadIdx.x;
    if (id < 4096) {
        float s = 1.f / (1.f + expf(-A[id]));
        int a = id >> 10, t = id & 1023;
        float cur = 1.f;
        #pragma unroll
        for (int v = 0; v < VPOW; v++) {
            g_Apow[(a * VPOW + v) * 1024 + t] = cur;
            cur *= s;
        }
    } else if (id < 4096 + 2048) {
        int j = id - 4096;
        const float* B = (j < 1024) ? B1 : B2;
        g_Bsig[j] = 1.f / (1.f + expf(-B[j & 1023]));
    }
}

// ---------------- 1b. C transpose: Ct[kd][d][n][h] = C_d[(h*64+kd)*16+n]/4 ---
__global__ void k_ct(const float* __restrict__ C1, const float* __restrict__ C2) {
    int id = blockIdx.x * 256 + threadIdx.x;      // 131072 total
    int h  = id & 63;
    int n  = (id >> 6) & 15;
    int d  = (id >> 10) & 1;
    int kd = id >> 11;
    const float* C = d ? C2 : C1;
    g_Ct[id] = C[(h * 64 + kd) * 16 + n] * 0.25f;
}

// ---------------- 2. one-hot index extraction from one_matrix ---------------
__global__ void k_extract(const float* __restrict__ OM) {
    int gwarp = (blockIdx.x * 256 + threadIdx.x) >> 5;
    int lane  = threadIdx.x & 31;
    int d   = gwarp / (5 * RTOT);
    int rem = gwarp - d * 5 * RTOT;
    int a   = rem / RTOT;
    int r   = rem - a * RTOT;
    int base = ((d * 5 + a) * RTOT + r) * VPOW;
    float v0 = OM[base + lane];
    float v1 = OM[base + 32 + lane];
    unsigned m0 = __ballot_sync(0xffffffffu, v0 != 0.f);
    unsigned m1 = __ballot_sync(0xffffffffu, v1 != 0.f);
    int idx = m0 ? (__ffs(m0) - 1) : (32 + __ffs(m1) - 1);
    if (a < 4) {
        if (lane == 0) g_idx8[(d * RTOT + r) * 4 + a] = (unsigned char)idx;
    } else {
        float val = __shfl_sync(0xffffffffu, (idx < 32) ? v0 : v1, idx & 31);
        if (lane == 0) g_coef[d * RTOT + r] = (idx == 0) ? val : -val;
    }
}

// ---------------- 3. w[d][p][kd*16+n], smem-tiled Apow gathers ---------------
// grid (32 tc, 8 pc, 2 d), 256 threads: (plane = tid>>5) x (t = tid&31)
__global__ void k_w() {
    __shared__ float sA[4 * VPOW * 32];            // 32 KB Apow slice for t-chunk
    int tc = blockIdx.x, pc = blockIdx.y, d = blockIdx.z;
    int t = threadIdx.x & 31, plane = threadIdx.x >> 5;
    for (int row = plane; row < 256; row += 8)
        sA[row * 32 + t] = g_Apow[row * 1024 + tc * 32 + t];
    __syncthreads();
    int tg = tc * 32 + t;
    float b0 = g_Bsig[tg], b1 = g_Bsig[1024 + tg];
    const unsigned* idx4p = (const unsigned*)g_idx8;
    for (int piter = 0; piter < 16; piter++) {
        int p = pc * 128 + piter * 8 + plane;
        float acc = 0.f;
        int rb = d * RTOT + p * 16;
        #pragma unroll
        for (int r2 = 0; r2 < R2; r2++) {
            unsigned q = idx4p[rb + r2];
            float cf  = g_coef[rb + r2];
            int i0 = q & 63, i1 = (q >> 8) & 63, i2 = (q >> 16) & 63, i3 = (q >> 24) & 63;
            float term = sA[(0 * VPOW + i0) * 32 + t] * sA[(1 * VPOW + i1) * 32 + t]
                       * sA[(2 * VPOW + i2) * 32 + t] * sA[(3 * VPOW + i3) * 32 + t];
            acc = fmaf(term * fabsf(cf), (cf > 0.f) ? b0 : b1, acc);
        }
        g_w[(d * 1024 + p) * 1024 + tg] = acc;
    }
}

// ---------------- 4. kk = W x C, smem GEMM, high occupancy -------------------
// grid (64 kd, 16 pc), 256 threads. Block: 64 p x 64 h, K = 32 (d,n).
__global__ void k_kk() {
    __shared__ float Csm[32 * 64];                 // [c][h], c=(d*16+n)
    __shared__ float Wsm[32 * 66];                 // [c][p_l], padded
    int kd = blockIdx.x, pc = blockIdx.y, tid = threadIdx.x;
    int p0 = pc * 64;
    const float* ct = g_Ct + kd * 2048;
    for (int idx = tid; idx < 2048; idx += 256)
        Csm[idx] = ct[idx];                        // Ct is [d][n][h] contiguous
    for (int idx = tid; idx < 2048; idx += 256) {
        int p_l = idx >> 5, c = idx & 31;
        int d = c >> 4, n = c & 15;
        Wsm[c * 66 + p_l] = g_w[(d * 1024 + p0 + p_l) * 1024 + kd * 16 + n];
    }
    __syncthreads();
    int pg = tid >> 3, hg = tid & 7;               // 32 p-pairs x 8 h-octets
    float acc[2][8];
    #pragma unroll
    for (int pi = 0; pi < 2; pi++)
        #pragma unroll
        for (int hi = 0; hi < 8; hi++) acc[pi][hi] = 0.f;
    #pragma unroll
    for (int c = 0; c < 32; c++) {
        float w0 = Wsm[c * 66 + pg * 2];
        float w1 = Wsm[c * 66 + pg * 2 + 1];
        float4 c0 = *(const float4*)&Csm[c * 64 + hg * 8];
        float4 c1 = *(const float4*)&Csm[c * 64 + hg * 8 + 4];
        float cc[8] = {c0.x, c0.y, c0.z, c0.w, c1.x, c1.y, c1.z, c1.w};
        #pragma unroll
        for (int hi = 0; hi < 8; hi++) {
            acc[0][hi] = fmaf(w0, cc[hi], acc[0][hi]);
            acc[1][hi] = fmaf(w1, cc[hi], acc[1][hi]);
        }
    }
    #pragma unroll
    for (int pi = 0; pi < 2; pi++) {
        int p = p0 + pg * 2 + pi;
        float4* dst = (float4*)&g_kk[p * 4096 + kd * 64 + hg * 8];
        dst[0] = make_float4(acc[pi][0], acc[pi][1], acc[pi][2], acc[pi][3]);
        dst[1] = make_float4(acc[pi][4], acc[pi][5], acc[pi][6], acc[pi][7]);
    }
}

// ---------------- 5. direction flips + boundary scaling → ksum[p][e] --------
__device__ __forceinline__ float bfactor(int a, int b) {
    float f = 1.f;
    if (a == 0) f *= 2.f;
    if (b == 0) f *= 2.f;
    if (a == 0 && b == 0) f *= 0.25f;
    return f;
}

__global__ void k_ksum() {
    __shared__ float sh[4][1024];
    int pi = blockIdx.x, pj = blockIdx.y, tid = threadIdx.x;
    int rows[4] = { pi * 32 + pj, (31 - pi) * 32 + pj,
                    pi * 32 + (31 - pj), (31 - pi) * 32 + (31 - pj) };
    #pragma unroll
    for (int dir = 0; dir < 4; dir++)
        for (int idx = tid; idx < 1024; idx += 256)
            sh[dir][idx] = g_kk[rows[dir] * 4096 + dir * 1024 + idx];
    __syncthreads();
    float f0 = bfactor(pi, pj), f1 = bfactor(31 - pi, pj);
    float f2 = bfactor(pi, 31 - pj), f3 = bfactor(31 - pi, 31 - pj);
    for (int e = tid; e < 1024; e += 256) {
        int h = e >> 4, s = e & 15;
        int o = s * 64 + h;
        float v = f0 * sh[0][o] + f1 * sh[1][o] + f2 * sh[2][o] + f3 * sh[3][o];
        g_ksum[(pi * 32 + pj) * 1024 + e] = v;
    }
}

// ---------------- 6. triangular conv, batch-pair f32x2, q-chunked k ----------
// grid (8 e-chunks, 32 i [big first], 4 batch-pairs), 128 threads.
// Regs: acc 64 + xr 64 + k2 16 + addr -> fits 3 blocks/SM.
__global__ void __launch_bounds__(128, 3)
k_conv(const float* __restrict__ x, const float* __restrict__ omega,
       float* __restrict__ out) {
    int e  = blockIdx.x * 128 + threadIdx.x;
    int i  = 31 - blockIdx.y;                      // heavy blocks launch first
    int b0 = blockIdx.z * 2;

    unsigned long long acc[32];                    // lanes = (b0, b0+1)
    #pragma unroll
    for (int j = 0; j < 32; j++) acc[j] = 0ull;
    unsigned long long xr[32];

    const float* xa = x + b0 * 1024 + e;           // advances by row each u
    const float* ka = g_ksum + (i * 32) * 1024 + e;// retreats by row each u

    #pragma unroll 1
    for (int u = 0; u <= i; u++) {
        #pragma unroll
        for (int j = 0; j < 32; j++)
            xr[j] = pk2(xa[j * 8192], xa[j * 8192 + 1024]);
        #pragma unroll
        for (int qc = 0; qc < 4; qc++) {
            unsigned long long k2[8];
            #pragma unroll
            for (int t = 0; t < 8; t++) {
                float kv = ka[(qc * 8 + t) * 1024];
                k2[t] = pk2(kv, kv);
            }
            #pragma unroll
            for (int j = qc * 8; j < 32; j++) {
                int qmax = (j < qc * 8 + 7) ? j : (qc * 8 + 7);
                #pragma unroll
                for (int q = qc * 8; q <= qmax; q++)
                    fma2(acc[j], k2[q - qc * 8], xr[j - q]);
            }
        }
        xa += 32 * 8192;                           // next x grid-row
        ka -= 32 * 1024;                           // previous kernel grid-row
    }

    // xr holds x grid-row i (last u) -> fused residual
    float om = omega[e];
    unsigned long long omp = pk2(om, om);
    float* oa = out + ((i * 32) * 8 + b0) * 1024 + e;
    #pragma unroll
    for (int j = 0; j < 32; j++) {
        fma2(acc[j], omp, xr[j]);
        float2 v = upk2(acc[j]);
        oa[j * 8192]        = v.x;
        oa[j * 8192 + 1024] = v.y;
    }
}

// ---------------- launch -----------------------------------------------------
extern "C" void kernel_launch(void* const* d_in, const int* in_sizes, int n_in,
                              void* d_out, int out_size) {
    const float* x   = (const float*)d_in[0];
    const float* A   = (const float*)d_in[1];
    const float* B1  = (const float*)d_in[2];
    const float* B2  = (const float*)d_in[3];
    const float* C1  = (const float*)d_in[4];
    const float* C2  = (const float*)d_in[5];
    const float* om  = (const float*)d_in[6];
    const float* OM  = (const float*)d_in[7];
    float* out = (float*)d_out;

    k_setup<<<24, 256>>>(A, B1, B2);
    k_ct<<<512, 256>>>(C1, C2);
    k_extract<<<(2 * 5 * RTOT) / 8, 256>>>(OM);
    k_w<<<dim3(32, 8, 2), 256>>>();
    k_kk<<<dim3(64, 16), 256>>>();
    k_ksum<<<dim3(32, 32), 256>>>();
    k_conv<<<dim3(8, 32, 4), 128>>>(x, om, out);
}